// round 1
// baseline (speedup 1.0000x reference)
#include <cuda_runtime.h>
#include <cstdint>

#define T_DIM 2048
#define S_DIM 2048
#define B_DIM 2
#define E_DIM 256
#define H_DIM 8
#define DH    32
#define SCALE 0.17677669529663687f   // 1/sqrt(32)

// Scratch (device globals: no allocation allowed in kernel_launch)
__device__ float g_qproj[(size_t)T_DIM * B_DIM * E_DIM];
__device__ float g_kproj[(size_t)S_DIM * B_DIM * E_DIM];
__device__ float g_attnout[(size_t)T_DIM * B_DIM * E_DIM];

// ---------------- packed f32x2 helpers (sm_103a FFMA2 path) ----------------
__device__ __forceinline__ void fma2(uint64_t &acc, uint64_t a, uint64_t b) {
    asm("fma.rn.f32x2 %0, %1, %2, %0;" : "+l"(acc) : "l"(a), "l"(b));
}
__device__ __forceinline__ uint64_t add2(uint64_t a, uint64_t b) {
    uint64_t d; asm("add.rn.f32x2 %0, %1, %2;" : "=l"(d) : "l"(a), "l"(b));
    return d;
}
__device__ __forceinline__ float lo_f(uint64_t v) { return __uint_as_float((uint32_t)v); }
__device__ __forceinline__ float hi_f(uint64_t v) { return __uint_as_float((uint32_t)(v >> 32)); }
__device__ __forceinline__ uint64_t pack2(float lo, float hi) {
    return (uint64_t)__float_as_uint(lo) | ((uint64_t)__float_as_uint(hi) << 32);
}

// ---------------------------------------------------------------------------
// proj_kernel: Y[r][f] = sum_e X[r][e] * W[f][e] + bias[f] (+ X[r][f] if residual)
// rows = 4096, E = 256. Block: 32 rows x 256 cols, thread = output column f.
// ---------------------------------------------------------------------------
__global__ __launch_bounds__(256) void proj_kernel(
    const float* __restrict__ X, const float* __restrict__ W,
    const float* __restrict__ bias, float* __restrict__ Y,
    int add_residual)
{
    __shared__ float Xs[32][32];
    __shared__ float Ws[256][36];   // pad 36 floats: conflict-free LDS.128

    const int tid = threadIdx.x;
    const int r0  = blockIdx.x * 32;

    float acc[32];
#pragma unroll
    for (int r = 0; r < 32; r++) acc[r] = 0.f;

    for (int e0 = 0; e0 < E_DIM; e0 += 32) {
        __syncthreads();
        // W chunk [256][32], coalesced
#pragma unroll
        for (int i = 0; i < 32; i++) {
            int idx = tid + i * 256;
            int f = idx >> 5, e = idx & 31;
            Ws[f][e] = W[(size_t)f * E_DIM + e0 + e];
        }
        // X chunk [32][32]
#pragma unroll
        for (int i = 0; i < 4; i++) {
            int ii = tid + i * 256;
            int r = ii >> 5, e = ii & 31;
            Xs[r][e] = X[(size_t)(r0 + r) * E_DIM + e0 + e];
        }
        __syncthreads();

        // hoist this thread's W row chunk into packed regs
        uint64_t w2[16];
#pragma unroll
        for (int j = 0; j < 8; j++) {
            ulonglong2 t = *(const ulonglong2*)&Ws[tid][j * 4];
            w2[2 * j]     = t.x;
            w2[2 * j + 1] = t.y;
        }
#pragma unroll
        for (int r = 0; r < 32; r++) {
            uint64_t a0 = 0, a1 = 0;
#pragma unroll
            for (int j = 0; j < 8; j++) {
                ulonglong2 x = *(const ulonglong2*)&Xs[r][j * 4];  // broadcast
                fma2(a0, w2[2 * j],     x.x);
                fma2(a1, w2[2 * j + 1], x.y);
            }
            uint64_t s = add2(a0, a1);
            acc[r] += lo_f(s) + hi_f(s);
        }
    }

    const float bf = bias[tid];
#pragma unroll
    for (int r = 0; r < 32; r++) {
        size_t o = (size_t)(r0 + r) * E_DIM + tid;
        float v = acc[r] + bf;
        if (add_residual) v += X[o];
        Y[o] = v;
    }
}

// ---------------------------------------------------------------------------
// attn_kernel: block = (32 query rows, one batch). warp<->head, lane<->row.
// Pass 1: l[t,h] = sum_s exp(score) (no max-sub needed; |score| <~ 6).
// Pass 2: p = exp(score)/l; accumulate out; stage p in smem; reduce over heads
//         and write avg_weights.
// ---------------------------------------------------------------------------
__global__ __launch_bounds__(256, 1) void attn_kernel(
    const float* __restrict__ value,
    float* __restrict__ avgw,
    float* __restrict__ attn_out)
{
    extern __shared__ float sm[];
    float* Ks = sm;                       // 64*256
    float* Vs = sm + 64 * 256;            // 64*256
    float* Ps = sm + 2 * 64 * 256;        // 8*32*65 (padded)

    const int tid = threadIdx.x;
    const int h   = tid >> 5;
    const int l   = tid & 31;
    const int t0  = blockIdx.x * 32;
    const int b   = blockIdx.y;

    // this lane's q row chunk (head h, row t0+l): 32 floats = 16 packed regs
    uint64_t q2[16];
    {
        const ulonglong2* qr = (const ulonglong2*)(g_qproj +
            ((size_t)(t0 + l) * B_DIM + b) * E_DIM + h * DH);
#pragma unroll
        for (int j = 0; j < 8; j++) { ulonglong2 t = qr[j]; q2[2*j] = t.x; q2[2*j+1] = t.y; }
    }

    // ------------------- pass 1: sum of exp -------------------
    float lsum = 0.f;
    for (int s0 = 0; s0 < S_DIM; s0 += 64) {
        __syncthreads();
#pragma unroll
        for (int i = 0; i < 16; i++) {
            int idx = tid + i * 256;               // 4096 float4 units
            int row = idx >> 6, c4 = idx & 63;
            *(float4*)&Ks[row * 256 + c4 * 4] =
                *(const float4*)&g_kproj[((size_t)(s0 + row) * B_DIM + b) * E_DIM + c4 * 4];
        }
        __syncthreads();
        const float* kb = Ks + h * DH;
#pragma unroll 2
        for (int s = 0; s < 64; s++) {
            const ulonglong2* kr = (const ulonglong2*)(kb + s * 256);
            uint64_t a0 = 0, a1 = 0, a2 = 0, a3 = 0;
#pragma unroll
            for (int j = 0; j < 2; j++) {
                ulonglong2 u = kr[4*j+0], v = kr[4*j+1], w = kr[4*j+2], x = kr[4*j+3];
                fma2(a0, q2[8*j+0], u.x); fma2(a1, q2[8*j+1], u.y);
                fma2(a2, q2[8*j+2], v.x); fma2(a3, q2[8*j+3], v.y);
                fma2(a0, q2[8*j+4], w.x); fma2(a1, q2[8*j+5], w.y);
                fma2(a2, q2[8*j+6], x.x); fma2(a3, q2[8*j+7], x.y);
            }
            uint64_t sf = add2(add2(a0, a1), add2(a2, a3));
            float score = lo_f(sf) + hi_f(sf);
            lsum += __expf(score * SCALE);
        }
    }
    const float inv_l = 1.f / lsum;

    // ------------------- pass 2: probs, out, avg_weights -------------------
    uint64_t o2[16];
#pragma unroll
    for (int j = 0; j < 16; j++) o2[j] = 0;

    for (int s0 = 0; s0 < S_DIM; s0 += 64) {
        __syncthreads();
#pragma unroll
        for (int i = 0; i < 16; i++) {
            int idx = tid + i * 256;
            int row = idx >> 6, c4 = idx & 63;
            *(float4*)&Ks[row * 256 + c4 * 4] =
                *(const float4*)&g_kproj[((size_t)(s0 + row) * B_DIM + b) * E_DIM + c4 * 4];
            *(float4*)&Vs[row * 256 + c4 * 4] =
                *(const float4*)&value[((size_t)(s0 + row) * B_DIM + b) * E_DIM + c4 * 4];
        }
        __syncthreads();
        const float* kb = Ks + h * DH;
        const float* vb = Vs + h * DH;
        float* prow = Ps + (size_t)(h * 32 + l) * 65;

        for (int s = 0; s < 64; s++) {
            const ulonglong2* kr = (const ulonglong2*)(kb + s * 256);
            uint64_t a0 = 0, a1 = 0, a2 = 0, a3 = 0;
#pragma unroll
            for (int j = 0; j < 2; j++) {
                ulonglong2 u = kr[4*j+0], v = kr[4*j+1], w = kr[4*j+2], x = kr[4*j+3];
                fma2(a0, q2[8*j+0], u.x); fma2(a1, q2[8*j+1], u.y);
                fma2(a2, q2[8*j+2], v.x); fma2(a3, q2[8*j+3], v.y);
                fma2(a0, q2[8*j+4], w.x); fma2(a1, q2[8*j+5], w.y);
                fma2(a2, q2[8*j+6], x.x); fma2(a3, q2[8*j+7], x.y);
            }
            uint64_t sf = add2(add2(a0, a1), add2(a2, a3));
            float score = lo_f(sf) + hi_f(sf);
            float p = __expf(score * SCALE) * inv_l;
            prow[s] = p;                       // stride-65 STS: conflict-free
            uint64_t pp = pack2(p, p);
            const ulonglong2* vr = (const ulonglong2*)(vb + s * 256);
#pragma unroll
            for (int j = 0; j < 8; j++) {
                ulonglong2 vv = vr[j];
                fma2(o2[2*j],     pp, vv.x);
                fma2(o2[2*j + 1], pp, vv.y);
            }
        }
        __syncthreads();

        // reduce over heads, write avg_weights tile [32 rows][64 s]
        {
            int row = tid >> 3;
            int sb  = (tid & 7) * 8;
            float out8[8];
#pragma unroll
            for (int j = 0; j < 8; j++) {
                float acc = 0.f;
#pragma unroll
                for (int hh = 0; hh < 8; hh++)
                    acc += Ps[(size_t)(hh * 32 + row) * 65 + sb + j];
                out8[j] = acc * 0.125f;
            }
            size_t o = (size_t)b * T_DIM * S_DIM + (size_t)(t0 + row) * S_DIM + s0 + sb;
            *(float4*)&avgw[o]     = make_float4(out8[0], out8[1], out8[2], out8[3]);
            *(float4*)&avgw[o + 4] = make_float4(out8[4], out8[5], out8[6], out8[7]);
        }
    }

    // write pre-projection attention output
    {
        float* orow = attn_out + ((size_t)(t0 + l) * B_DIM + b) * E_DIM + h * DH;
#pragma unroll
        for (int j = 0; j < 8; j++) {
            ulonglong2 t; t.x = o2[2*j]; t.y = o2[2*j+1];
            *(ulonglong2*)&orow[j * 4] = t;
        }
    }
}

// ---------------------------------------------------------------------------
extern "C" void kernel_launch(void* const* d_in, const int* in_sizes, int n_in,
                              void* d_out, int out_size)
{
    (void)in_sizes; (void)n_in; (void)out_size;

    const float* query = (const float*)d_in[0];
    const float* key   = (const float*)d_in[1];
    const float* value = (const float*)d_in[2];
    const float* Wq    = (const float*)d_in[3];
    const float* bq    = (const float*)d_in[4];
    const float* Wk    = (const float*)d_in[5];
    const float* bk    = (const float*)d_in[6];
    const float* Wo    = (const float*)d_in[7];
    const float* bo    = (const float*)d_in[8];

    float* out  = (float*)d_out;
    float* avgw = out + (size_t)T_DIM * B_DIM * E_DIM;

    float *qp = nullptr, *kp = nullptr, *ao = nullptr;
    cudaGetSymbolAddress((void**)&qp, g_qproj);
    cudaGetSymbolAddress((void**)&kp, g_kproj);
    cudaGetSymbolAddress((void**)&ao, g_attnout);

    const int rows_blocks = (T_DIM * B_DIM) / 32;   // 128

    // Q and K projections
    proj_kernel<<<rows_blocks, 256>>>(query, Wq, bq, qp, 0);
    proj_kernel<<<rows_blocks, 256>>>(key,   Wk, bk, kp, 0);

    // fused attention + softmax + avg_weights + PV
    const int smem_bytes = (2 * 64 * 256 + 8 * 32 * 65) * (int)sizeof(float);  // 197632
    cudaFuncSetAttribute(attn_kernel, cudaFuncAttributeMaxDynamicSharedMemorySize, smem_bytes);
    attn_kernel<<<dim3(T_DIM / 32, B_DIM), 256, smem_bytes>>>(value, avgw, ao);

    // residual output projection
    proj_kernel<<<rows_blocks, 256>>>(ao, Wo, bo, out, 1);
}

// round 2
// speedup vs baseline: 1.7386x; 1.7386x over previous
#include <cuda_runtime.h>
#include <cstdint>

#define T_DIM 2048
#define S_DIM 2048
#define B_DIM 2
#define E_DIM 256
#define H_DIM 8
#define DH    32
// (1/sqrt(32)) * log2(e)
#define SCLOG2E 0.25503511091247115f

// Scratch (device globals: no allocation allowed in kernel_launch)
__device__ float g_qproj[(size_t)T_DIM * B_DIM * E_DIM];
__device__ float g_kproj[(size_t)S_DIM * B_DIM * E_DIM];
__device__ float g_attnout[(size_t)T_DIM * B_DIM * E_DIM];

// ---------------- packed f32x2 helpers (kept for proj kernel) ----------------
__device__ __forceinline__ void fma2(uint64_t &acc, uint64_t a, uint64_t b) {
    asm("fma.rn.f32x2 %0, %1, %2, %0;" : "+l"(acc) : "l"(a), "l"(b));
}
__device__ __forceinline__ uint64_t add2(uint64_t a, uint64_t b) {
    uint64_t d; asm("add.rn.f32x2 %0, %1, %2;" : "=l"(d) : "l"(a), "l"(b));
    return d;
}
__device__ __forceinline__ float lo_f(uint64_t v) { return __uint_as_float((uint32_t)v); }
__device__ __forceinline__ float hi_f(uint64_t v) { return __uint_as_float((uint32_t)(v >> 32)); }

// ---------------- tf32 MMA helpers ----------------
__device__ __forceinline__ uint32_t f2tf32(float f) {
    uint32_t r; asm("cvt.rna.tf32.f32 %0, %1;" : "=r"(r) : "f"(f)); return r;
}
__device__ __forceinline__ float tf2f(uint32_t u) { return __uint_as_float(u); }
__device__ __forceinline__ float ex2f(float x) {
    float y; asm("ex2.approx.f32 %0, %1;" : "=f"(y) : "f"(x)); return y;
}
// D += A(16x8) * B(8x8), tf32 inputs, f32 accum
__device__ __forceinline__ void mma_tf32(float* d, const uint32_t* a, const uint32_t* b) {
    asm volatile(
        "mma.sync.aligned.m16n8k8.row.col.f32.tf32.tf32.f32 "
        "{%0,%1,%2,%3}, {%4,%5,%6,%7}, {%8,%9}, {%0,%1,%2,%3};"
        : "+f"(d[0]), "+f"(d[1]), "+f"(d[2]), "+f"(d[3])
        : "r"(a[0]), "r"(a[1]), "r"(a[2]), "r"(a[3]), "r"(b[0]), "r"(b[1]));
}

// padded smem strides (all fragment gathers conflict-free)
#define KSTR 260   // 260 % 32 == 4 : bank = 4*s + k, s in 0..7, k in 0..3 -> distinct
#define VSTR 264   // 264 % 32 == 8 : bank = 8*s + d, s in 0..3, d in 0..7 -> distinct
#define PSTR 68    //  68 % 32 == 4 : bank = 4*t + s, t in 0..7, s in 0..3 -> distinct
#define PHEAD (32 * PSTR)

// ---------------------------------------------------------------------------
// proj_kernel: Y[r][f] = sum_e X[r][e] * W[f][e] + bias[f] (+ X[r][f] if residual)
// ---------------------------------------------------------------------------
__global__ __launch_bounds__(256) void proj_kernel(
    const float* __restrict__ X, const float* __restrict__ W,
    const float* __restrict__ bias, float* __restrict__ Y,
    int add_residual)
{
    __shared__ float Xs[32][32];
    __shared__ float Ws[256][36];

    const int tid = threadIdx.x;
    const int r0  = blockIdx.x * 32;

    float acc[32];
#pragma unroll
    for (int r = 0; r < 32; r++) acc[r] = 0.f;

    for (int e0 = 0; e0 < E_DIM; e0 += 32) {
        __syncthreads();
#pragma unroll
        for (int i = 0; i < 32; i++) {
            int idx = tid + i * 256;
            int f = idx >> 5, e = idx & 31;
            Ws[f][e] = W[(size_t)f * E_DIM + e0 + e];
        }
#pragma unroll
        for (int i = 0; i < 4; i++) {
            int ii = tid + i * 256;
            int r = ii >> 5, e = ii & 31;
            Xs[r][e] = X[(size_t)(r0 + r) * E_DIM + e0 + e];
        }
        __syncthreads();

        uint64_t w2[16];
#pragma unroll
        for (int j = 0; j < 8; j++) {
            ulonglong2 t = *(const ulonglong2*)&Ws[tid][j * 4];
            w2[2 * j]     = t.x;
            w2[2 * j + 1] = t.y;
        }
#pragma unroll
        for (int r = 0; r < 32; r++) {
            uint64_t a0 = 0, a1 = 0;
#pragma unroll
            for (int j = 0; j < 8; j++) {
                ulonglong2 x = *(const ulonglong2*)&Xs[r][j * 4];
                fma2(a0, w2[2 * j],     x.x);
                fma2(a1, w2[2 * j + 1], x.y);
            }
            uint64_t s = add2(a0, a1);
            acc[r] += lo_f(s) + hi_f(s);
        }
    }

    const float bf = bias[tid];
#pragma unroll
    for (int r = 0; r < 32; r++) {
        size_t o = (size_t)(r0 + r) * E_DIM + tid;
        float v = acc[r] + bf;
        if (add_residual) v += X[o];
        Y[o] = v;
    }
}

// ---------------------------------------------------------------------------
// attn_tc_kernel: tensor-core attention.
// Block = (32 q rows, one batch), warp <-> head. 3xTF32 QK^T, 1xTF32 PV.
// Pass 1: row sums of exp(score). Pass 2: p, PV, avg_weights via smem Ps.
// ---------------------------------------------------------------------------
__global__ __launch_bounds__(256, 1) void attn_tc_kernel(
    const float* __restrict__ value,
    float* __restrict__ avgw,
    float* __restrict__ attn_out)
{
    extern __shared__ float sm[];
    float* Ks = sm;                         // 64 * KSTR
    float* Vs = sm + 64 * KSTR;             // 64 * VSTR
    float* Ps = Vs + 64 * VSTR;             // 8 * 32 * PSTR

    const int tid  = threadIdx.x;
    const int h    = tid >> 5;
    const int lane = tid & 31;
    const int g    = lane >> 2;      // 0..7
    const int tig  = lane & 3;       // 0..3
    const int t0   = blockIdx.x * 32;
    const int b    = blockIdx.y;
    const int hb   = h * DH;

    // ---- load Q fragments (hi/lo split for 3xTF32) ----
    uint32_t qhi[2][4][4], qlo[2][4][4];
#pragma unroll
    for (int mt = 0; mt < 2; mt++) {
#pragma unroll
        for (int j = 0; j < 4; j++) {
            int r = t0 + mt * 16 + g;
            int c = hb + j * 8 + tig;
            float v0 = g_qproj[((size_t)r       * B_DIM + b) * E_DIM + c];
            float v1 = g_qproj[((size_t)(r + 8) * B_DIM + b) * E_DIM + c];
            float v2 = g_qproj[((size_t)r       * B_DIM + b) * E_DIM + c + 4];
            float v3 = g_qproj[((size_t)(r + 8) * B_DIM + b) * E_DIM + c + 4];
            qhi[mt][j][0] = f2tf32(v0); qlo[mt][j][0] = f2tf32(v0 - tf2f(qhi[mt][j][0]));
            qhi[mt][j][1] = f2tf32(v1); qlo[mt][j][1] = f2tf32(v1 - tf2f(qhi[mt][j][1]));
            qhi[mt][j][2] = f2tf32(v2); qlo[mt][j][2] = f2tf32(v2 - tf2f(qhi[mt][j][2]));
            qhi[mt][j][3] = f2tf32(v3); qlo[mt][j][3] = f2tf32(v3 - tf2f(qhi[mt][j][3]));
        }
    }

    // ================= pass 1: row sums of exp =================
    float lsum[4] = {0.f, 0.f, 0.f, 0.f};

    for (int s0 = 0; s0 < S_DIM; s0 += 64) {
        __syncthreads();
#pragma unroll
        for (int i = 0; i < 16; i++) {
            int idx = tid + i * 256;
            int row = idx >> 6, c4 = idx & 63;
            *(float4*)&Ks[row * KSTR + c4 * 4] =
                *(const float4*)&g_kproj[((size_t)(s0 + row) * B_DIM + b) * E_DIM + c4 * 4];
        }
        __syncthreads();

#pragma unroll
        for (int half = 0; half < 2; half++) {
            const int soff = half * 32;
            float d[2][4][4];
#pragma unroll
            for (int mt = 0; mt < 2; mt++)
#pragma unroll
                for (int nt = 0; nt < 4; nt++)
#pragma unroll
                    for (int r = 0; r < 4; r++) d[mt][nt][r] = 0.f;

#pragma unroll
            for (int j = 0; j < 4; j++) {
                uint32_t bh[4][2], bl[4][2];
#pragma unroll
                for (int nt = 0; nt < 4; nt++) {
                    float k0 = Ks[(soff + nt * 8 + g) * KSTR + hb + j * 8 + tig];
                    float k1 = Ks[(soff + nt * 8 + g) * KSTR + hb + j * 8 + tig + 4];
                    bh[nt][0] = f2tf32(k0); bl[nt][0] = f2tf32(k0 - tf2f(bh[nt][0]));
                    bh[nt][1] = f2tf32(k1); bl[nt][1] = f2tf32(k1 - tf2f(bh[nt][1]));
                }
#pragma unroll
                for (int nt = 0; nt < 4; nt++) {
                    mma_tf32(d[0][nt], qhi[0][j], bh[nt]);
                    mma_tf32(d[1][nt], qhi[1][j], bh[nt]);
                }
#pragma unroll
                for (int nt = 0; nt < 4; nt++) {
                    mma_tf32(d[0][nt], qlo[0][j], bh[nt]);
                    mma_tf32(d[1][nt], qlo[1][j], bh[nt]);
                }
#pragma unroll
                for (int nt = 0; nt < 4; nt++) {
                    mma_tf32(d[0][nt], qhi[0][j], bl[nt]);
                    mma_tf32(d[1][nt], qhi[1][j], bl[nt]);
                }
            }
#pragma unroll
            for (int mt = 0; mt < 2; mt++)
#pragma unroll
                for (int nt = 0; nt < 4; nt++)
#pragma unroll
                    for (int r = 0; r < 4; r++)
                        lsum[mt * 2 + (r >> 1)] += ex2f(d[mt][nt][r] * SCLOG2E);
        }
    }
#pragma unroll
    for (int r = 0; r < 4; r++) {
        lsum[r] += __shfl_xor_sync(0xffffffffu, lsum[r], 1);
        lsum[r] += __shfl_xor_sync(0xffffffffu, lsum[r], 2);
    }
    float inv[4];
#pragma unroll
    for (int r = 0; r < 4; r++) inv[r] = 1.0f / lsum[r];

    // ================= pass 2 =================
    float o[2][4][4];
#pragma unroll
    for (int mt = 0; mt < 2; mt++)
#pragma unroll
        for (int nd = 0; nd < 4; nd++)
#pragma unroll
            for (int r = 0; r < 4; r++) o[mt][nd][r] = 0.f;

    for (int s0 = 0; s0 < S_DIM; s0 += 64) {
        __syncthreads();
#pragma unroll
        for (int i = 0; i < 16; i++) {
            int idx = tid + i * 256;
            int row = idx >> 6, c4 = idx & 63;
            *(float4*)&Ks[row * KSTR + c4 * 4] =
                *(const float4*)&g_kproj[((size_t)(s0 + row) * B_DIM + b) * E_DIM + c4 * 4];
            *(float4*)&Vs[row * VSTR + c4 * 4] =
                *(const float4*)&value[((size_t)(s0 + row) * B_DIM + b) * E_DIM + c4 * 4];
        }
        __syncthreads();

#pragma unroll
        for (int half = 0; half < 2; half++) {
            const int soff = half * 32;
            float d[2][4][4];
#pragma unroll
            for (int mt = 0; mt < 2; mt++)
#pragma unroll
                for (int nt = 0; nt < 4; nt++)
#pragma unroll
                    for (int r = 0; r < 4; r++) d[mt][nt][r] = 0.f;

#pragma unroll
            for (int j = 0; j < 4; j++) {
                uint32_t bh[4][2], bl[4][2];
#pragma unroll
                for (int nt = 0; nt < 4; nt++) {
                    float k0 = Ks[(soff + nt * 8 + g) * KSTR + hb + j * 8 + tig];
                    float k1 = Ks[(soff + nt * 8 + g) * KSTR + hb + j * 8 + tig + 4];
                    bh[nt][0] = f2tf32(k0); bl[nt][0] = f2tf32(k0 - tf2f(bh[nt][0]));
                    bh[nt][1] = f2tf32(k1); bl[nt][1] = f2tf32(k1 - tf2f(bh[nt][1]));
                }
#pragma unroll
                for (int nt = 0; nt < 4; nt++) {
                    mma_tf32(d[0][nt], qhi[0][j], bh[nt]);
                    mma_tf32(d[1][nt], qhi[1][j], bh[nt]);
                }
#pragma unroll
                for (int nt = 0; nt < 4; nt++) {
                    mma_tf32(d[0][nt], qlo[0][j], bh[nt]);
                    mma_tf32(d[1][nt], qlo[1][j], bh[nt]);
                }
#pragma unroll
                for (int nt = 0; nt < 4; nt++) {
                    mma_tf32(d[0][nt], qhi[0][j], bl[nt]);
                    mma_tf32(d[1][nt], qhi[1][j], bl[nt]);
                }
            }

            // normalize, stage p into Ps
#pragma unroll
            for (int mt = 0; mt < 2; mt++) {
#pragma unroll
                for (int nt = 0; nt < 4; nt++) {
                    float p0 = ex2f(d[mt][nt][0] * SCLOG2E) * inv[mt * 2 + 0];
                    float p1 = ex2f(d[mt][nt][1] * SCLOG2E) * inv[mt * 2 + 0];
                    float p2 = ex2f(d[mt][nt][2] * SCLOG2E) * inv[mt * 2 + 1];
                    float p3 = ex2f(d[mt][nt][3] * SCLOG2E) * inv[mt * 2 + 1];
                    int scol = soff + nt * 8 + 2 * tig;
                    *(float2*)&Ps[h * PHEAD + (mt * 16 + g)     * PSTR + scol] = make_float2(p0, p1);
                    *(float2*)&Ps[h * PHEAD + (mt * 16 + g + 8) * PSTR + scol] = make_float2(p2, p3);
                }
            }
            __syncwarp();

            // PV: A = p (from Ps), B = V (from Vs), 1xTF32
#pragma unroll
            for (int ks = 0; ks < 4; ks++) {
                uint32_t a[2][4];
#pragma unroll
                for (int mt = 0; mt < 2; mt++) {
                    int rb = mt * 16;
                    int sc = soff + ks * 8 + tig;
                    a[mt][0] = f2tf32(Ps[h * PHEAD + (rb + g)     * PSTR + sc]);
                    a[mt][1] = f2tf32(Ps[h * PHEAD + (rb + g + 8) * PSTR + sc]);
                    a[mt][2] = f2tf32(Ps[h * PHEAD + (rb + g)     * PSTR + sc + 4]);
                    a[mt][3] = f2tf32(Ps[h * PHEAD + (rb + g + 8) * PSTR + sc + 4]);
                }
#pragma unroll
                for (int nd = 0; nd < 4; nd++) {
                    uint32_t bb[2];
                    bb[0] = f2tf32(Vs[(soff + ks * 8 + tig)     * VSTR + hb + nd * 8 + g]);
                    bb[1] = f2tf32(Vs[(soff + ks * 8 + tig + 4) * VSTR + hb + nd * 8 + g]);
                    mma_tf32(o[0][nd], a[0], bb);
                    mma_tf32(o[1][nd], a[1], bb);
                }
            }
        }
        __syncthreads();

        // avg_weights: reduce Ps over heads, write [32 x 64] tile
        {
            int row = tid >> 3;
            int sb  = (tid & 7) * 8;
            float4 A = make_float4(0.f, 0.f, 0.f, 0.f);
            float4 C = make_float4(0.f, 0.f, 0.f, 0.f);
#pragma unroll
            for (int hh = 0; hh < 8; hh++) {
                float4 x = *(const float4*)&Ps[hh * PHEAD + row * PSTR + sb];
                float4 y = *(const float4*)&Ps[hh * PHEAD + row * PSTR + sb + 4];
                A.x += x.x; A.y += x.y; A.z += x.z; A.w += x.w;
                C.x += y.x; C.y += y.y; C.z += y.z; C.w += y.w;
            }
            A.x *= 0.125f; A.y *= 0.125f; A.z *= 0.125f; A.w *= 0.125f;
            C.x *= 0.125f; C.y *= 0.125f; C.z *= 0.125f; C.w *= 0.125f;
            size_t oo = (size_t)b * T_DIM * S_DIM + (size_t)(t0 + row) * S_DIM + s0 + sb;
            *(float4*)&avgw[oo]     = A;
            *(float4*)&avgw[oo + 4] = C;
        }
    }

    // write pre-projection attention output
#pragma unroll
    for (int mt = 0; mt < 2; mt++) {
#pragma unroll
        for (int nd = 0; nd < 4; nd++) {
            int col = hb + nd * 8 + 2 * tig;
            size_t b0 = ((size_t)(t0 + mt * 16 + g)     * B_DIM + b) * E_DIM + col;
            size_t b1 = ((size_t)(t0 + mt * 16 + g + 8) * B_DIM + b) * E_DIM + col;
            *(float2*)&attn_out[b0] = make_float2(o[mt][nd][0], o[mt][nd][1]);
            *(float2*)&attn_out[b1] = make_float2(o[mt][nd][2], o[mt][nd][3]);
        }
    }
}

// ---------------------------------------------------------------------------
extern "C" void kernel_launch(void* const* d_in, const int* in_sizes, int n_in,
                              void* d_out, int out_size)
{
    (void)in_sizes; (void)n_in; (void)out_size;

    const float* query = (const float*)d_in[0];
    const float* key   = (const float*)d_in[1];
    const float* value = (const float*)d_in[2];
    const float* Wq    = (const float*)d_in[3];
    const float* bq    = (const float*)d_in[4];
    const float* Wk    = (const float*)d_in[5];
    const float* bk    = (const float*)d_in[6];
    const float* Wo    = (const float*)d_in[7];
    const float* bo    = (const float*)d_in[8];

    float* out  = (float*)d_out;
    float* avgw = out + (size_t)T_DIM * B_DIM * E_DIM;

    float *qp = nullptr, *kp = nullptr, *ao = nullptr;
    cudaGetSymbolAddress((void**)&qp, g_qproj);
    cudaGetSymbolAddress((void**)&kp, g_kproj);
    cudaGetSymbolAddress((void**)&ao, g_attnout);

    const int rows_blocks = (T_DIM * B_DIM) / 32;   // 128

    proj_kernel<<<rows_blocks, 256>>>(query, Wq, bq, qp, 0);
    proj_kernel<<<rows_blocks, 256>>>(key,   Wk, bk, kp, 0);

    const int smem_bytes = (64 * KSTR + 64 * VSTR + 8 * 32 * PSTR) * (int)sizeof(float); // 203776
    cudaFuncSetAttribute(attn_tc_kernel, cudaFuncAttributeMaxDynamicSharedMemorySize, smem_bytes);
    attn_tc_kernel<<<dim3(T_DIM / 32, B_DIM), 256, smem_bytes>>>(value, avgw, ao);

    proj_kernel<<<rows_blocks, 256>>>(ao, Wo, bo, out, 1);
}

// round 3
// speedup vs baseline: 2.3889x; 1.3740x over previous
#include <cuda_runtime.h>
#include <cstdint>

#define T_DIM 2048
#define S_DIM 2048
#define B_DIM 2
#define E_DIM 256
#define H_DIM 8
#define DH    32
// (1/sqrt(32)) * log2(e)
#define SCLOG2E 0.25503511091247115f

// Scratch (device globals: no allocation allowed in kernel_launch)
__device__ float g_qproj[(size_t)T_DIM * B_DIM * E_DIM];
__device__ float g_kproj[(size_t)S_DIM * B_DIM * E_DIM];
__device__ float g_attnout[(size_t)T_DIM * B_DIM * E_DIM];

// ---------------- conversion helpers ----------------
__device__ __forceinline__ uint32_t f2tf32(float f) {
    uint32_t r; asm("cvt.rna.tf32.f32 %0, %1;" : "=r"(r) : "f"(f)); return r;
}
__device__ __forceinline__ float tf2f(uint32_t u) { return __uint_as_float(u); }
__device__ __forceinline__ float ex2f(float x) {
    float y; asm("ex2.approx.f32 %0, %1;" : "=f"(y) : "f"(x)); return y;
}
// pack (lo, hi) floats into bf16x2 word: bits[15:0] = lo element (even index)
__device__ __forceinline__ uint32_t bfpack(float hi, float lo) {
    uint32_t r; asm("cvt.rn.bf16x2.f32 %0, %1, %2;" : "=r"(r) : "f"(hi), "f"(lo)); return r;
}
__device__ __forceinline__ float bflo_f(uint32_t u) { return __uint_as_float(u << 16); }
__device__ __forceinline__ float bfhi_f(uint32_t u) { return __uint_as_float(u & 0xffff0000u); }

// D += A(16x8) * B(8x8), tf32 inputs, f32 accum
__device__ __forceinline__ void mma_tf32(float* d, const uint32_t* a, const uint32_t* b) {
    asm volatile(
        "mma.sync.aligned.m16n8k8.row.col.f32.tf32.tf32.f32 "
        "{%0,%1,%2,%3}, {%4,%5,%6,%7}, {%8,%9}, {%0,%1,%2,%3};"
        : "+f"(d[0]), "+f"(d[1]), "+f"(d[2]), "+f"(d[3])
        : "r"(a[0]), "r"(a[1]), "r"(a[2]), "r"(a[3]), "r"(b[0]), "r"(b[1]));
}
// D += A(16x16) * B(16x8), bf16 inputs, f32 accum
__device__ __forceinline__ void mma_bf16(float* d, const uint32_t* a, const uint32_t* b) {
    asm volatile(
        "mma.sync.aligned.m16n8k16.row.col.f32.bf16.bf16.f32 "
        "{%0,%1,%2,%3}, {%4,%5,%6,%7}, {%8,%9}, {%0,%1,%2,%3};"
        : "+f"(d[0]), "+f"(d[1]), "+f"(d[2]), "+f"(d[3])
        : "r"(a[0]), "r"(a[1]), "r"(a[2]), "r"(a[3]), "r"(b[0]), "r"(b[1]));
}

// smem strides
#define KWSTR 132  // uint32 words per K row (128 data + 4 pad); 132%32=4 -> conflict-free frags
#define VSTR  264  // floats per V row
#define PSTR  68   // floats per P row
#define PHEAD (32 * PSTR)

// ---------------------------------------------------------------------------
// proj_tc_kernel: Y[r][f] = sum_e X[r][e]*W[f][e] + bias[f] (+X[r][f] if res)
// 3xTF32 tensor-core version. Block: 32 rows x 256 cols (8 warps, 32 cols each).
// ---------------------------------------------------------------------------
__device__ __forceinline__ void proj_tc_body(
    const float* __restrict__ X, const float* __restrict__ W,
    const float* __restrict__ bias, float* __restrict__ Y,
    int add_residual, int r0)
{
    __shared__ float Xh[32][36], Xl[32][36];
    __shared__ float Ws[256][36];

    const int tid  = threadIdx.x;
    const int w    = tid >> 5;
    const int lane = tid & 31;
    const int g    = lane >> 2;
    const int tig  = lane & 3;

    float d[2][4][4];
#pragma unroll
    for (int mt = 0; mt < 2; mt++)
#pragma unroll
        for (int nt = 0; nt < 4; nt++)
#pragma unroll
            for (int r = 0; r < 4; r++) d[mt][nt][r] = 0.f;

    for (int e0 = 0; e0 < E_DIM; e0 += 32) {
        __syncthreads();
#pragma unroll
        for (int i = 0; i < 8; i++) {
            int idx = tid + i * 256;
            int n = idx >> 3, c4 = (idx & 7) * 4;
            float4 v = *(const float4*)&W[(size_t)n * E_DIM + e0 + c4];
            Ws[n][c4] = v.x; Ws[n][c4 + 1] = v.y; Ws[n][c4 + 2] = v.z; Ws[n][c4 + 3] = v.w;
        }
#pragma unroll
        for (int i = 0; i < 4; i++) {
            int idx = tid + i * 256;
            int r = idx >> 5, e = idx & 31;
            float v = X[(size_t)(r0 + r) * E_DIM + e0 + e];
            float h = tf2f(f2tf32(v));
            Xh[r][e] = h; Xl[r][e] = v - h;
        }
        __syncthreads();

#pragma unroll
        for (int k8 = 0; k8 < 4; k8++) {
            uint32_t ah[2][4], al[2][4];
#pragma unroll
            for (int mt = 0; mt < 2; mt++) {
                int rA = mt * 16 + g;
                ah[mt][0] = __float_as_uint(Xh[rA][k8 * 8 + tig]);
                ah[mt][1] = __float_as_uint(Xh[rA + 8][k8 * 8 + tig]);
                ah[mt][2] = __float_as_uint(Xh[rA][k8 * 8 + tig + 4]);
                ah[mt][3] = __float_as_uint(Xh[rA + 8][k8 * 8 + tig + 4]);
                al[mt][0] = f2tf32(Xl[rA][k8 * 8 + tig]);
                al[mt][1] = f2tf32(Xl[rA + 8][k8 * 8 + tig]);
                al[mt][2] = f2tf32(Xl[rA][k8 * 8 + tig + 4]);
                al[mt][3] = f2tf32(Xl[rA + 8][k8 * 8 + tig + 4]);
            }
#pragma unroll
            for (int nt = 0; nt < 4; nt++) {
                int n = w * 32 + nt * 8 + g;
                float w0 = Ws[n][k8 * 8 + tig], w1 = Ws[n][k8 * 8 + tig + 4];
                uint32_t bh[2], bl[2];
                bh[0] = f2tf32(w0); bl[0] = f2tf32(w0 - tf2f(bh[0]));
                bh[1] = f2tf32(w1); bl[1] = f2tf32(w1 - tf2f(bh[1]));
                mma_tf32(d[0][nt], ah[0], bh);
                mma_tf32(d[1][nt], ah[1], bh);
                mma_tf32(d[0][nt], al[0], bh);
                mma_tf32(d[1][nt], al[1], bh);
                mma_tf32(d[0][nt], ah[0], bl);
                mma_tf32(d[1][nt], ah[1], bl);
            }
        }
    }

#pragma unroll
    for (int mt = 0; mt < 2; mt++) {
#pragma unroll
        for (int nt = 0; nt < 4; nt++) {
            int c = w * 32 + nt * 8 + 2 * tig;
            float b0 = __ldg(&bias[c]), b1 = __ldg(&bias[c + 1]);
            size_t o0 = (size_t)(r0 + mt * 16 + g) * E_DIM + c;
            size_t o1 = (size_t)(r0 + mt * 16 + g + 8) * E_DIM + c;
            float y0 = d[mt][nt][0] + b0, y1 = d[mt][nt][1] + b1;
            float y2 = d[mt][nt][2] + b0, y3 = d[mt][nt][3] + b1;
            if (add_residual) {
                float2 x0 = *(const float2*)&X[o0];
                float2 x1 = *(const float2*)&X[o1];
                y0 += x0.x; y1 += x0.y; y2 += x1.x; y3 += x1.y;
            }
            *(float2*)&Y[o0] = make_float2(y0, y1);
            *(float2*)&Y[o1] = make_float2(y2, y3);
        }
    }
}

// merged Q+K projection: blockIdx.y selects stream
__global__ __launch_bounds__(256) void proj_qk_kernel(
    const float* __restrict__ Xq, const float* __restrict__ Wq, const float* __restrict__ bq,
    const float* __restrict__ Xk, const float* __restrict__ Wk, const float* __restrict__ bk,
    float* __restrict__ Yq, float* __restrict__ Yk)
{
    int r0 = blockIdx.x * 32;
    if (blockIdx.y == 0) proj_tc_body(Xq, Wq, bq, Yq, 0, r0);
    else                 proj_tc_body(Xk, Wk, bk, Yk, 0, r0);
}

__global__ __launch_bounds__(256) void proj_o_kernel(
    const float* __restrict__ X, const float* __restrict__ W,
    const float* __restrict__ bias, float* __restrict__ Y)
{
    proj_tc_body(X, W, bias, Y, 1, blockIdx.x * 32);
}

// ---------------------------------------------------------------------------
// attn_tc_kernel: block = (32 q rows, one batch), warp <-> head.
// QK^T: 2-split bf16 (3 MMA terms, m16n8k16). PV: 1xTF32.
// K tiles stored in smem pre-split as packed bf16x2 hi/lo words.
// ---------------------------------------------------------------------------
__global__ __launch_bounds__(256, 1) void attn_tc_kernel(
    const float* __restrict__ value,
    float* __restrict__ avgw,
    float* __restrict__ attn_out)
{
    extern __shared__ uint32_t smu[];
    uint32_t* Kh = smu;                          // 64 * KWSTR words (bf16x2 hi)
    uint32_t* Kl = smu + 64 * KWSTR;             // 64 * KWSTR words (bf16x2 lo)
    float*    Vs = (float*)(smu + 2 * 64 * KWSTR); // 64 * VSTR floats
    float*    Ps = Vs + 64 * VSTR;               // 8 * 32 * PSTR floats

    const int tid  = threadIdx.x;
    const int h    = tid >> 5;
    const int lane = tid & 31;
    const int g    = lane >> 2;
    const int tig  = lane & 3;
    const int t0   = blockIdx.x * 32;
    const int b    = blockIdx.y;
    const int hb   = h * DH;
    const int hw   = hb >> 1;                    // word offset of head in K rows

    // ---- Q fragments: bf16 2-split, m16n8k16 A layout ----
    // qh/ql[mt][jc][0..3]; jc selects k16 chunk (k = hb + jc*16 ...)
    uint32_t qh[2][2][4], ql[2][2][4];
#pragma unroll
    for (int mt = 0; mt < 2; mt++) {
#pragma unroll
        for (int jc = 0; jc < 2; jc++) {
            int r = t0 + mt * 16 + g;
            int c = hb + jc * 16 + 2 * tig;
            float2 v0 = *(const float2*)&g_qproj[((size_t)r       * B_DIM + b) * E_DIM + c];
            float2 v1 = *(const float2*)&g_qproj[((size_t)(r + 8) * B_DIM + b) * E_DIM + c];
            float2 v2 = *(const float2*)&g_qproj[((size_t)r       * B_DIM + b) * E_DIM + c + 8];
            float2 v3 = *(const float2*)&g_qproj[((size_t)(r + 8) * B_DIM + b) * E_DIM + c + 8];
            qh[mt][jc][0] = bfpack(v0.y, v0.x);
            qh[mt][jc][1] = bfpack(v1.y, v1.x);
            qh[mt][jc][2] = bfpack(v2.y, v2.x);
            qh[mt][jc][3] = bfpack(v3.y, v3.x);
            ql[mt][jc][0] = bfpack(v0.y - bfhi_f(qh[mt][jc][0]), v0.x - bflo_f(qh[mt][jc][0]));
            ql[mt][jc][1] = bfpack(v1.y - bfhi_f(qh[mt][jc][1]), v1.x - bflo_f(qh[mt][jc][1]));
            ql[mt][jc][2] = bfpack(v2.y - bfhi_f(qh[mt][jc][2]), v2.x - bflo_f(qh[mt][jc][2]));
            ql[mt][jc][3] = bfpack(v3.y - bfhi_f(qh[mt][jc][3]), v3.x - bflo_f(qh[mt][jc][3]));
        }
    }

    // ================= pass 1: row sums of exp =================
    float lsum[4] = {0.f, 0.f, 0.f, 0.f};

    for (int s0 = 0; s0 < S_DIM; s0 += 64) {
        __syncthreads();
#pragma unroll
        for (int i = 0; i < 16; i++) {
            int idx = tid + i * 256;
            int row = idx >> 6, c4 = idx & 63;
            float4 v = *(const float4*)&g_kproj[((size_t)(s0 + row) * B_DIM + b) * E_DIM + c4 * 4];
            uint32_t h0 = bfpack(v.y, v.x);
            uint32_t h1 = bfpack(v.w, v.z);
            uint32_t l0 = bfpack(v.y - bfhi_f(h0), v.x - bflo_f(h0));
            uint32_t l1 = bfpack(v.w - bfhi_f(h1), v.z - bflo_f(h1));
            *(uint2*)&Kh[row * KWSTR + 2 * c4] = make_uint2(h0, h1);
            *(uint2*)&Kl[row * KWSTR + 2 * c4] = make_uint2(l0, l1);
        }
        __syncthreads();

#pragma unroll
        for (int half = 0; half < 2; half++) {
            const int soff = half * 32;
            float d[2][4][4];
#pragma unroll
            for (int mt = 0; mt < 2; mt++)
#pragma unroll
                for (int nt = 0; nt < 4; nt++)
#pragma unroll
                    for (int r = 0; r < 4; r++) d[mt][nt][r] = 0.f;

#pragma unroll
            for (int jc = 0; jc < 2; jc++) {
                uint32_t bh[4][2], bl[4][2];
#pragma unroll
                for (int nt = 0; nt < 4; nt++) {
                    int base = (soff + nt * 8 + g) * KWSTR + hw + jc * 8 + tig;
                    bh[nt][0] = Kh[base]; bh[nt][1] = Kh[base + 4];
                    bl[nt][0] = Kl[base]; bl[nt][1] = Kl[base + 4];
                }
#pragma unroll
                for (int nt = 0; nt < 4; nt++) {
                    mma_bf16(d[0][nt], qh[0][jc], bh[nt]);
                    mma_bf16(d[1][nt], qh[1][jc], bh[nt]);
                }
#pragma unroll
                for (int nt = 0; nt < 4; nt++) {
                    mma_bf16(d[0][nt], ql[0][jc], bh[nt]);
                    mma_bf16(d[1][nt], ql[1][jc], bh[nt]);
                }
#pragma unroll
                for (int nt = 0; nt < 4; nt++) {
                    mma_bf16(d[0][nt], qh[0][jc], bl[nt]);
                    mma_bf16(d[1][nt], qh[1][jc], bl[nt]);
                }
            }
#pragma unroll
            for (int mt = 0; mt < 2; mt++)
#pragma unroll
                for (int nt = 0; nt < 4; nt++)
#pragma unroll
                    for (int r = 0; r < 4; r++)
                        lsum[mt * 2 + (r >> 1)] += ex2f(d[mt][nt][r] * SCLOG2E);
        }
    }
#pragma unroll
    for (int r = 0; r < 4; r++) {
        lsum[r] += __shfl_xor_sync(0xffffffffu, lsum[r], 1);
        lsum[r] += __shfl_xor_sync(0xffffffffu, lsum[r], 2);
    }
    float inv[4];
#pragma unroll
    for (int r = 0; r < 4; r++) inv[r] = 1.0f / lsum[r];

    // ================= pass 2 =================
    float o[2][4][4];
#pragma unroll
    for (int mt = 0; mt < 2; mt++)
#pragma unroll
        for (int nd = 0; nd < 4; nd++)
#pragma unroll
            for (int r = 0; r < 4; r++) o[mt][nd][r] = 0.f;

    for (int s0 = 0; s0 < S_DIM; s0 += 64) {
        __syncthreads();
#pragma unroll
        for (int i = 0; i < 16; i++) {
            int idx = tid + i * 256;
            int row = idx >> 6, c4 = idx & 63;
            float4 v = *(const float4*)&g_kproj[((size_t)(s0 + row) * B_DIM + b) * E_DIM + c4 * 4];
            uint32_t h0 = bfpack(v.y, v.x);
            uint32_t h1 = bfpack(v.w, v.z);
            uint32_t l0 = bfpack(v.y - bfhi_f(h0), v.x - bflo_f(h0));
            uint32_t l1 = bfpack(v.w - bfhi_f(h1), v.z - bflo_f(h1));
            *(uint2*)&Kh[row * KWSTR + 2 * c4] = make_uint2(h0, h1);
            *(uint2*)&Kl[row * KWSTR + 2 * c4] = make_uint2(l0, l1);
            *(float4*)&Vs[row * VSTR + c4 * 4] =
                *(const float4*)&value[((size_t)(s0 + row) * B_DIM + b) * E_DIM + c4 * 4];
        }
        __syncthreads();

#pragma unroll
        for (int half = 0; half < 2; half++) {
            const int soff = half * 32;
            float d[2][4][4];
#pragma unroll
            for (int mt = 0; mt < 2; mt++)
#pragma unroll
                for (int nt = 0; nt < 4; nt++)
#pragma unroll
                    for (int r = 0; r < 4; r++) d[mt][nt][r] = 0.f;

#pragma unroll
            for (int jc = 0; jc < 2; jc++) {
                uint32_t bh[4][2], bl[4][2];
#pragma unroll
                for (int nt = 0; nt < 4; nt++) {
                    int base = (soff + nt * 8 + g) * KWSTR + hw + jc * 8 + tig;
                    bh[nt][0] = Kh[base]; bh[nt][1] = Kh[base + 4];
                    bl[nt][0] = Kl[base]; bl[nt][1] = Kl[base + 4];
                }
#pragma unroll
                for (int nt = 0; nt < 4; nt++) {
                    mma_bf16(d[0][nt], qh[0][jc], bh[nt]);
                    mma_bf16(d[1][nt], qh[1][jc], bh[nt]);
                }
#pragma unroll
                for (int nt = 0; nt < 4; nt++) {
                    mma_bf16(d[0][nt], ql[0][jc], bh[nt]);
                    mma_bf16(d[1][nt], ql[1][jc], bh[nt]);
                }
#pragma unroll
                for (int nt = 0; nt < 4; nt++) {
                    mma_bf16(d[0][nt], qh[0][jc], bl[nt]);
                    mma_bf16(d[1][nt], qh[1][jc], bl[nt]);
                }
            }

            // normalize, stage p into Ps
#pragma unroll
            for (int mt = 0; mt < 2; mt++) {
#pragma unroll
                for (int nt = 0; nt < 4; nt++) {
                    float p0 = ex2f(d[mt][nt][0] * SCLOG2E) * inv[mt * 2 + 0];
                    float p1 = ex2f(d[mt][nt][1] * SCLOG2E) * inv[mt * 2 + 0];
                    float p2 = ex2f(d[mt][nt][2] * SCLOG2E) * inv[mt * 2 + 1];
                    float p3 = ex2f(d[mt][nt][3] * SCLOG2E) * inv[mt * 2 + 1];
                    int scol = soff + nt * 8 + 2 * tig;
                    *(float2*)&Ps[h * PHEAD + (mt * 16 + g)     * PSTR + scol] = make_float2(p0, p1);
                    *(float2*)&Ps[h * PHEAD + (mt * 16 + g + 8) * PSTR + scol] = make_float2(p2, p3);
                }
            }
            __syncwarp();

            // PV: A = p (from Ps), B = V (from Vs), 1xTF32
#pragma unroll
            for (int ks = 0; ks < 4; ks++) {
                uint32_t a[2][4];
#pragma unroll
                for (int mt = 0; mt < 2; mt++) {
                    int rb = mt * 16;
                    int sc = soff + ks * 8 + tig;
                    a[mt][0] = f2tf32(Ps[h * PHEAD + (rb + g)     * PSTR + sc]);
                    a[mt][1] = f2tf32(Ps[h * PHEAD + (rb + g + 8) * PSTR + sc]);
                    a[mt][2] = f2tf32(Ps[h * PHEAD + (rb + g)     * PSTR + sc + 4]);
                    a[mt][3] = f2tf32(Ps[h * PHEAD + (rb + g + 8) * PSTR + sc + 4]);
                }
#pragma unroll
                for (int nd = 0; nd < 4; nd++) {
                    uint32_t bb[2];
                    bb[0] = f2tf32(Vs[(soff + ks * 8 + tig)     * VSTR + hb + nd * 8 + g]);
                    bb[1] = f2tf32(Vs[(soff + ks * 8 + tig + 4) * VSTR + hb + nd * 8 + g]);
                    mma_tf32(o[0][nd], a[0], bb);
                    mma_tf32(o[1][nd], a[1], bb);
                }
            }
        }
        __syncthreads();

        // avg_weights: reduce Ps over heads, write [32 x 64] tile
        {
            int row = tid >> 3;
            int sb  = (tid & 7) * 8;
            float4 A = make_float4(0.f, 0.f, 0.f, 0.f);
            float4 C = make_float4(0.f, 0.f, 0.f, 0.f);
#pragma unroll
            for (int hh = 0; hh < 8; hh++) {
                float4 x = *(const float4*)&Ps[hh * PHEAD + row * PSTR + sb];
                float4 y = *(const float4*)&Ps[hh * PHEAD + row * PSTR + sb + 4];
                A.x += x.x; A.y += x.y; A.z += x.z; A.w += x.w;
                C.x += y.x; C.y += y.y; C.z += y.z; C.w += y.w;
            }
            A.x *= 0.125f; A.y *= 0.125f; A.z *= 0.125f; A.w *= 0.125f;
            C.x *= 0.125f; C.y *= 0.125f; C.z *= 0.125f; C.w *= 0.125f;
            size_t oo = (size_t)b * T_DIM * S_DIM + (size_t)(t0 + row) * S_DIM + s0 + sb;
            *(float4*)&avgw[oo]     = A;
            *(float4*)&avgw[oo + 4] = C;
        }
    }

    // write pre-projection attention output
#pragma unroll
    for (int mt = 0; mt < 2; mt++) {
#pragma unroll
        for (int nd = 0; nd < 4; nd++) {
            int col = hb + nd * 8 + 2 * tig;
            size_t b0 = ((size_t)(t0 + mt * 16 + g)     * B_DIM + b) * E_DIM + col;
            size_t b1 = ((size_t)(t0 + mt * 16 + g + 8) * B_DIM + b) * E_DIM + col;
            *(float2*)&attn_out[b0] = make_float2(o[mt][nd][0], o[mt][nd][1]);
            *(float2*)&attn_out[b1] = make_float2(o[mt][nd][2], o[mt][nd][3]);
        }
    }
}

// ---------------------------------------------------------------------------
extern "C" void kernel_launch(void* const* d_in, const int* in_sizes, int n_in,
                              void* d_out, int out_size)
{
    (void)in_sizes; (void)n_in; (void)out_size;

    const float* query = (const float*)d_in[0];
    const float* key   = (const float*)d_in[1];
    const float* value = (const float*)d_in[2];
    const float* Wq    = (const float*)d_in[3];
    const float* bq    = (const float*)d_in[4];
    const float* Wk    = (const float*)d_in[5];
    const float* bk    = (const float*)d_in[6];
    const float* Wo    = (const float*)d_in[7];
    const float* bo    = (const float*)d_in[8];

    float* out  = (float*)d_out;
    float* avgw = out + (size_t)T_DIM * B_DIM * E_DIM;

    float *qp = nullptr, *kp = nullptr, *ao = nullptr;
    cudaGetSymbolAddress((void**)&qp, g_qproj);
    cudaGetSymbolAddress((void**)&kp, g_kproj);
    cudaGetSymbolAddress((void**)&ao, g_attnout);

    const int rows_blocks = (T_DIM * B_DIM) / 32;   // 128

    // Q and K projections (merged launch)
    proj_qk_kernel<<<dim3(rows_blocks, 2), 256>>>(query, Wq, bq, key, Wk, bk, qp, kp);

    // fused attention + softmax + avg_weights + PV
    const int smem_bytes = (2 * 64 * KWSTR + 64 * VSTR + 8 * 32 * PSTR) * 4;  // 204800
    cudaFuncSetAttribute(attn_tc_kernel, cudaFuncAttributeMaxDynamicSharedMemorySize, smem_bytes);
    attn_tc_kernel<<<dim3(T_DIM / 32, B_DIM), 256, smem_bytes>>>(value, avgw, ao);

    // residual output projection
    proj_o_kernel<<<rows_blocks, 256>>>(ao, Wo, bo, out);
}